// round 8
// baseline (speedup 1.0000x reference)
#include <cuda_runtime.h>
#include <cuda_bf16.h>
#include <cstdint>

#define NROWS 32768
#define CCLS  2048
#define DDIM  512

// ---- GEMM tiling ----
#define BM 128
#define BN 256
#define BK 64                    // bf16 elems per chunk (128B per row)
#define KCHUNKS 24               // 3 products x (512/64)
#define A_BYTES 16384            // 128 rows x 128B
#define B_BYTES 32768            // 256 rows x 128B
#define STAGE_BYTES (A_BYTES + B_BYTES)       // 49152
#define NSTAGES 3
#define SMEM_TOTAL  (NSTAGES * STAGE_BYTES)   // 147456

// ---- scratch (__device__ globals; no cudaMalloc allowed) ----
__device__ __nv_bfloat16 g_Ah[(size_t)NROWS * DDIM];
__device__ __nv_bfloat16 g_Al[(size_t)NROWS * DDIM];
__device__ __nv_bfloat16 g_Bh[(size_t)CCLS * DDIM];
__device__ __nv_bfloat16 g_Bl[(size_t)CCLS * DDIM];
__device__ float g_m2[CCLS];

// ===========================================================================
// PTX helpers (all supported on plain sm_103 target)
// ===========================================================================
__device__ __forceinline__ uint32_t smem_u32(const void* p) {
    uint32_t a;
    asm("{ .reg .u64 t; cvta.to.shared.u64 t, %1; cvt.u32.u64 %0, t; }" : "=r"(a) : "l"(p));
    return a;
}

__device__ __forceinline__ void cp16(uint32_t dst, const void* src) {
    asm volatile("cp.async.cg.shared.global.L2::128B [%0], [%1], 16;" :: "r"(dst), "l"(src));
}
#define CP_COMMIT() asm volatile("cp.async.commit_group;" ::: "memory")
#define CP_WAIT1()  asm volatile("cp.async.wait_group 1;" ::: "memory")

__device__ __forceinline__ void ldsm4(uint32_t* r, uint32_t addr) {
    asm volatile("ldmatrix.sync.aligned.m8n8.x4.shared.b16 {%0,%1,%2,%3}, [%4];"
                 : "=r"(r[0]), "=r"(r[1]), "=r"(r[2]), "=r"(r[3]) : "r"(addr));
}

__device__ __forceinline__ void mma16816(float* d, const uint32_t* a, const uint32_t* b) {
    asm volatile("mma.sync.aligned.m16n8k16.row.col.f32.bf16.bf16.f32 "
                 "{%0,%1,%2,%3}, {%4,%5,%6,%7}, {%8,%9}, {%0,%1,%2,%3};"
                 : "+f"(d[0]), "+f"(d[1]), "+f"(d[2]), "+f"(d[3])
                 : "r"(a[0]), "r"(a[1]), "r"(a[2]), "r"(a[3]), "r"(b[0]), "r"(b[1]));
}

// ===========================================================================
// Kernel: convert X -> bf16 hi/lo
// ===========================================================================
__global__ __launch_bounds__(256) void k_convX(const float* __restrict__ X) {
    const int idx = blockIdx.x * 256 + threadIdx.x;        // float4 index
    float4 v = ((const float4*)X)[idx];
    __nv_bfloat16 h0 = __float2bfloat16(v.x), h1 = __float2bfloat16(v.y);
    __nv_bfloat16 h2 = __float2bfloat16(v.z), h3 = __float2bfloat16(v.w);
    __nv_bfloat16 l0 = __float2bfloat16(v.x - __bfloat162float(h0));
    __nv_bfloat16 l1 = __float2bfloat16(v.y - __bfloat162float(h1));
    __nv_bfloat16 l2 = __float2bfloat16(v.z - __bfloat162float(h2));
    __nv_bfloat16 l3 = __float2bfloat16(v.w - __bfloat162float(h3));
    __nv_bfloat162* Ah = (__nv_bfloat162*)g_Ah;
    __nv_bfloat162* Al = (__nv_bfloat162*)g_Al;
    __nv_bfloat162 p;
    p.x = h0; p.y = h1; Ah[idx * 2]     = p;
    p.x = h2; p.y = h3; Ah[idx * 2 + 1] = p;
    p.x = l0; p.y = l1; Al[idx * 2]     = p;
    p.x = l2; p.y = l3; Al[idx * 2 + 1] = p;
}

// ===========================================================================
// Kernel: convert MU -> bf16 hi/lo, fused with m2[c] = ||mu_c||^2
// ===========================================================================
__global__ __launch_bounds__(128) void k_convMU(const float* __restrict__ MU) {
    const int c = blockIdx.x;
    const size_t base = (size_t)c * DDIM;
    float s = 0.f;
    #pragma unroll
    for (int j = 0; j < 4; j++) {
        int d = threadIdx.x + j * 128;
        float x = MU[base + d];
        __nv_bfloat16 h = __float2bfloat16(x);
        __nv_bfloat16 l = __float2bfloat16(x - __bfloat162float(h));
        g_Bh[base + d] = h;
        g_Bl[base + d] = l;
        s = fmaf(x, x, s);
    }
    #pragma unroll
    for (int o = 16; o; o >>= 1) s += __shfl_xor_sync(0xffffffffu, s, o);
    __shared__ float sm[4];
    if ((threadIdx.x & 31) == 0) sm[threadIdx.x >> 5] = s;
    __syncthreads();
    if (threadIdx.x == 0) g_m2[c] = sm[0] + sm[1] + sm[2] + sm[3];
}

// ===========================================================================
// Kernel: HMMA GEMM  S[i][j] = 2*(x_i . mu_j) - m2[j]
// Virtual K = 1536: phase 0 = Ah.Bh, phase 1 = Al.Bh, phase 2 = Ah.Bl
// 128x256 CTA tile, 8 warps of 64x64 (2x4), 1 CTA/SM, 3-stage cp.async.
// ===========================================================================
__device__ __forceinline__ void load_chunk(uint32_t stb, int t,
                                           int bm, int bn, int tid) {
    const int phase = t >> 3;
    const int koff  = (t & 7) * BK;
    const __nv_bfloat16* A = (phase == 1) ? g_Al : g_Ah;
    const __nv_bfloat16* B = (phase == 2) ? g_Bl : g_Bh;
    const uint32_t bs = stb + A_BYTES;
    #pragma unroll
    for (int i = 0; i < 4; i++) {                 // A: 128 rows x 8 f4
        int q = tid + i * 256;
        int r = q >> 3, c = q & 7;
        uint32_t off = r * 128 + ((c * 16) ^ ((r & 7) << 4));
        cp16(stb + off, A + (size_t)(bm + r) * DDIM + koff + c * 8);
    }
    #pragma unroll
    for (int i = 0; i < 8; i++) {                 // B: 256 rows x 8 f4
        int q = tid + i * 256;
        int r = q >> 3, c = q & 7;
        uint32_t off = r * 128 + ((c * 16) ^ ((r & 7) << 4));
        cp16(bs + off, B + (size_t)(bn + r) * DDIM + koff + c * 8);
    }
}

__global__ __launch_bounds__(256, 1) void k_gemm_mma(float* __restrict__ S) {
    extern __shared__ char smem[];
    const uint32_t sb = smem_u32(smem);
    const int tid = threadIdx.x;
    const int wid = tid >> 5, l = tid & 31;
    const int bm = blockIdx.y * BM, bn = blockIdx.x * BN;
    const int wm = (wid & 1) * 64;      // warp row offset (64 rows)
    const int wn = (wid >> 1) * 64;     // warp col offset (64 cols)

    float acc[4][8][4];                 // [m-tile][n8-tile][frag]
    #pragma unroll
    for (int i = 0; i < 4; i++)
        #pragma unroll
        for (int j = 0; j < 8; j++)
            #pragma unroll
            for (int k = 0; k < 4; k++) acc[i][j][k] = 0.f;

    // per-lane ldmatrix addressing (swizzle nibble depends only on lane)
    const uint32_t sw   = (uint32_t)(l & 7) << 4;
    const int rowA = wm + (l & 15);                       // + mt*16
    const uint32_t aColSel = ((uint32_t)(l >> 4)) << 4;   // 0 / 16 bytes
    const int rowB = wn + ((l >> 4) << 3) + (l & 7);      // + bt*16
    const uint32_t bColSel = ((uint32_t)((l >> 3) & 1)) << 4;

    // prologue: chunks 0,1 -> stages 0,1
    load_chunk(sb + 0 * STAGE_BYTES, 0, bm, bn, tid); CP_COMMIT();
    load_chunk(sb + 1 * STAGE_BYTES, 1, bm, bn, tid); CP_COMMIT();

    int rs = 0;                         // read stage
    int ws = 2;                         // write stage
    for (int t = 0; t < KCHUNKS; t++) {
        CP_WAIT1();                     // chunk t resident
        __syncthreads();

        if (t + 2 < KCHUNKS) load_chunk(sb + ws * STAGE_BYTES, t + 2, bm, bn, tid);
        CP_COMMIT();                    // one group per iteration (possibly empty)

        const uint32_t as = sb + rs * STAGE_BYTES;
        const uint32_t bs = as + A_BYTES;

        #pragma unroll
        for (int ks = 0; ks < 4; ks++) {
            const uint32_t kb = (uint32_t)ks * 32;
            uint32_t a[4][4], b[4][4];
            #pragma unroll
            for (int bt = 0; bt < 4; bt++)
                ldsm4(b[bt], bs + (uint32_t)(rowB + bt * 16) * 128 + ((kb + bColSel) ^ sw));
            #pragma unroll
            for (int mt = 0; mt < 4; mt++)
                ldsm4(a[mt], as + (uint32_t)(rowA + mt * 16) * 128 + ((kb + aColSel) ^ sw));
            #pragma unroll
            for (int mt = 0; mt < 4; mt++) {
                #pragma unroll
                for (int bt = 0; bt < 4; bt++) {
                    mma16816(acc[mt][bt * 2],     a[mt], &b[bt][0]);
                    mma16816(acc[mt][bt * 2 + 1], a[mt], &b[bt][2]);
                }
            }
        }

        rs = (rs == 2) ? 0 : rs + 1;
        ws = (ws == 2) ? 0 : ws + 1;
    }

    // epilogue: d -> 2*d - m2[col]
    const int cbase = bn + wn + (l & 3) * 2;
    float m2v[8][2];
    #pragma unroll
    for (int nt = 0; nt < 8; nt++) {
        m2v[nt][0] = g_m2[cbase + nt * 8];
        m2v[nt][1] = g_m2[cbase + nt * 8 + 1];
    }
    const int rbase = bm + wm + (l >> 2);
    #pragma unroll
    for (int mt = 0; mt < 4; mt++) {
        #pragma unroll
        for (int nt = 0; nt < 8; nt++) {
            float2 v0, v1;
            v0.x = 2.f * acc[mt][nt][0] - m2v[nt][0];
            v0.y = 2.f * acc[mt][nt][1] - m2v[nt][1];
            v1.x = 2.f * acc[mt][nt][2] - m2v[nt][0];
            v1.y = 2.f * acc[mt][nt][3] - m2v[nt][1];
            const int r = rbase + mt * 16;
            const int c = cbase + nt * 8;
            *(float2*)(S + (size_t)r * CCLS + c)       = v0;
            *(float2*)(S + (size_t)(r + 8) * CCLS + c) = v1;
        }
    }
}

// ===========================================================================
// Kernel: per-row masked softmax, in place on S
// ===========================================================================
__device__ __forceinline__ float block_red(float v, int mode, float* sred, int tid) {
    #pragma unroll
    for (int o = 16; o; o >>= 1) {
        float t = __shfl_xor_sync(0xffffffffu, v, o);
        v = (mode == 0) ? fminf(v, t) : (mode == 1) ? fmaxf(v, t) : (v + t);
    }
    __syncthreads();
    if ((tid & 31) == 0) sred[tid >> 5] = v;
    __syncthreads();
    float r;
    if (mode == 0) {
        r = fminf(fminf(fminf(sred[0], sred[1]), fminf(sred[2], sred[3])),
                  fminf(fminf(sred[4], sred[5]), fminf(sred[6], sred[7])));
    } else if (mode == 1) {
        r = fmaxf(fmaxf(fmaxf(sred[0], sred[1]), fmaxf(sred[2], sred[3])),
                  fmaxf(fmaxf(sred[4], sred[5]), fmaxf(sred[6], sred[7])));
    } else {
        r = ((sred[0] + sred[1]) + (sred[2] + sred[3])) +
            ((sred[4] + sred[5]) + (sred[6] + sred[7]));
    }
    return r;
}

__global__ __launch_bounds__(256) void k_softmax(float* __restrict__ S,
                                                 const float* __restrict__ cK) {
    __shared__ float sred[8];
    const int row = blockIdx.x;
    const int tid = threadIdx.x;
    float4* sp = (float4*)(S + (size_t)row * CCLS);
    const float4* cp = (const float4*)cK;

    float4 v0 = sp[tid];
    float4 v1 = sp[tid + 256];
    float4 c0 = cp[tid];
    float4 c1 = cp[tid + 256];

    float mn = fminf(fminf(fminf(v0.x, v0.y), fminf(v0.z, v0.w)),
                     fminf(fminf(v1.x, v1.y), fminf(v1.z, v1.w)));
    mn = block_red(mn, 0, sred, tid);
    const float mval = mn - 1.f;

    v0.x = (c0.x == 0.f) ? mval : v0.x;
    v0.y = (c0.y == 0.f) ? mval : v0.y;
    v0.z = (c0.z == 0.f) ? mval : v0.z;
    v0.w = (c0.w == 0.f) ? mval : v0.w;
    v1.x = (c1.x == 0.f) ? mval : v1.x;
    v1.y = (c1.y == 0.f) ? mval : v1.y;
    v1.z = (c1.z == 0.f) ? mval : v1.z;
    v1.w = (c1.w == 0.f) ? mval : v1.w;

    float mx = fmaxf(fmaxf(fmaxf(v0.x, v0.y), fmaxf(v0.z, v0.w)),
                     fmaxf(fmaxf(v1.x, v1.y), fmaxf(v1.z, v1.w)));
    mx = block_red(mx, 1, sred, tid);

    float4 e0, e1;
    e0.x = __expf(v0.x - mx); e0.y = __expf(v0.y - mx);
    e0.z = __expf(v0.z - mx); e0.w = __expf(v0.w - mx);
    e1.x = __expf(v1.x - mx); e1.y = __expf(v1.y - mx);
    e1.z = __expf(v1.z - mx); e1.w = __expf(v1.w - mx);
    float sum = ((e0.x + e0.y) + (e0.z + e0.w)) + ((e1.x + e1.y) + (e1.z + e1.w));
    sum = block_red(sum, 2, sred, tid);
    const float inv = 1.f / sum;

    e0.x *= inv; e0.y *= inv; e0.z *= inv; e0.w *= inv;
    e1.x *= inv; e1.y *= inv; e1.z *= inv; e1.w *= inv;
    sp[tid]       = e0;
    sp[tid + 256] = e1;
}

// ===========================================================================
extern "C" void kernel_launch(void* const* d_in, const int* in_sizes, int n_in,
                              void* d_out, int out_size) {
    const float* X  = (const float*)d_in[0];   // (N, D) fp32
    const float* MU = (const float*)d_in[1];   // (C, D) fp32
    const float* cK = (const float*)d_in[2];   // (C,)   fp32
    float* out = (float*)d_out;                // (N, C) fp32

    cudaFuncSetAttribute(k_gemm_mma, cudaFuncAttributeMaxDynamicSharedMemorySize, SMEM_TOTAL);

    k_convX<<<(NROWS * DDIM) / 4 / 256, 256>>>(X);
    k_convMU<<<CCLS, 128>>>(MU);

    dim3 grid(CCLS / BN, NROWS / BM);          // (8, 256)
    k_gemm_mma<<<grid, 256, SMEM_TOTAL>>>(out);

    k_softmax<<<NROWS, 256>>>(out, cK);
}